// round 1
// baseline (speedup 1.0000x reference)
#include <cuda_runtime.h>

// Haar pair transform: x (64, 4096, 256) f32 -> out (64, 2048, 512) f32
// Chunk-local: each 512-float contiguous chunk maps to itself:
//   out[2f]   = (in[f] + in[f+256]) * INV_SQRT2
//   out[2f+1] = (in[f] - in[f+256]) * INV_SQRT2
// One thread per float4 of output: two float2 loads + one float4 store,
// all perfectly coalesced.

__constant__ float kInvSqrt2 = 0.70710678118654752440f;

__global__ void __launch_bounds__(256) haar_kernel(
    const float2* __restrict__ in2,   // input viewed as float2
    float4* __restrict__ out4,        // output viewed as float4
    int n4)                           // total float4 outputs
{
    int t = blockIdx.x * blockDim.x + threadIdx.x;
    if (t >= n4) return;

    const float c = kInvSqrt2;

    int chunk = t >> 7;        // 128 float4 outputs per 512-float chunk
    int j     = t & 127;       // pair index within chunk (covers f=2j, 2j+1)

    int base2 = (chunk << 8) + j;      // float2 index of x0 pair
    float2 a = in2[base2];             // in[f], in[f+1]        (f = 2j)
    float2 b = in2[base2 + 128];       // in[f+256], in[f+257]

    float4 o;
    o.x = (a.x + b.x) * c;   // cA[f]
    o.y = (a.x - b.x) * c;   // cD[f]
    o.z = (a.y + b.y) * c;   // cA[f+1]
    o.w = (a.y - b.y) * c;   // cD[f+1]

    out4[t] = o;
}

extern "C" void kernel_launch(void* const* d_in, const int* in_sizes, int n_in,
                              void* d_out, int out_size)
{
    const float* x = (const float*)d_in[0];
    float* out = (float*)d_out;

    int n4 = out_size / 4;                       // 16,777,216 float4 stores
    int threads = 256;
    int blocks = (n4 + threads - 1) / threads;   // 65,536 blocks

    haar_kernel<<<blocks, threads>>>(
        (const float2*)x, (float4*)out, n4);
}